// round 15
// baseline (speedup 1.0000x reference)
#include <cuda_runtime.h>
#include <cuda_fp16.h>
#include <cstdint>

// ---------------- problem constants ----------------
#define T_LEN   2048
#define BATCH   64
#define IDIM    128
#define HDIM    128
#define FCDIM   32
#define ODIM    2
#define TCH     64                  // timesteps per chunk (MMA N)
#define CHUNKS  (T_LEN / TCH)       // 32
#define NTH     512                 // 16 warps: 4m x 4n, warp tile m32 x n16

// ---------------- global scratch -------------------------------------------
__device__ __align__(16) __half g_wH[3 * BATCH * HDIM * IDIM];  // fp16 W (g,i,f)
__device__ float2 g_AB[BATCH * CHUNKS * HDIM];                  // chunk affine (A,B)

// ---------------- SMEM layout (bytes) --------------------------------------
// x tile 64 x 256B = 16384 | W tiles 3 x 128 x 256B = 98304.
// seg (float2[128][4] = 4KB) aliases the x region after the mainloop.
#define SM_X     0
#define SM_W     16384
#define SM_TOTAL 114688             // x2 CTAs = 229376 <= 233472 (228KB)

// ---------------- helpers ---------------------------------------------------
__device__ __forceinline__ uint32_t smem_u32(const void* p) {
    uint32_t a;
    asm("{ .reg .u64 t; cvta.to.shared.u64 t, %1; cvt.u32.u64 %0, t; }"
        : "=r"(a) : "l"(p));
    return a;
}
__device__ __forceinline__ void cp_async16(uint32_t dst, const void* src) {
    asm volatile("cp.async.cg.shared.global [%0], [%1], 16;"
                 :: "r"(dst), "l"(src) : "memory");
}
__device__ __forceinline__ void cp_commit_wait() {
    asm volatile("cp.async.commit_group;" ::: "memory");
    asm volatile("cp.async.wait_group 0;" ::: "memory");
}
__device__ __forceinline__ void ldsm_x4(uint32_t (&r)[4], uint32_t addr) {
    asm volatile("ldmatrix.sync.aligned.m8n8.x4.shared.b16 {%0,%1,%2,%3}, [%4];"
                 : "=r"(r[0]), "=r"(r[1]), "=r"(r[2]), "=r"(r[3]) : "r"(addr));
}
__device__ __forceinline__ void mma_f16(float (&d)[4], const uint32_t (&a)[4],
                                        uint32_t b0, uint32_t b1) {
    asm volatile("mma.sync.aligned.m16n8k16.row.col.f32.f16.f16.f32 "
                 "{%0,%1,%2,%3}, {%4,%5,%6,%7}, {%8,%9}, {%0,%1,%2,%3};"
                 : "+f"(d[0]), "+f"(d[1]), "+f"(d[2]), "+f"(d[3])
                 : "r"(a[0]), "r"(a[1]), "r"(a[2]), "r"(a[3]), "r"(b0), "r"(b1));
}
// pack 8 fp32 -> 8 fp16
__device__ __forceinline__ uint4 cvt8h(float4 a, float4 b) {
    uint4 r;
    r.x = __half_as_ushort(__float2half_rn(a.x)) |
          ((uint32_t)__half_as_ushort(__float2half_rn(a.y)) << 16);
    r.y = __half_as_ushort(__float2half_rn(a.z)) |
          ((uint32_t)__half_as_ushort(__float2half_rn(a.w)) << 16);
    r.z = __half_as_ushort(__float2half_rn(b.x)) |
          ((uint32_t)__half_as_ushort(__float2half_rn(b.y)) << 16);
    r.w = __half_as_ushort(__float2half_rn(b.z)) |
          ((uint32_t)__half_as_ushort(__float2half_rn(b.w)) << 16);
    return r;
}
// exact sigmoid (2 MUFU) — used for the f gate only (error compounds in A=prod f)
__device__ __forceinline__ float fsig(float x)  { return 1.0f / (1.0f + __expf(-x)); }
// 1-MUFU tanh (sm_75+): abs err ~5e-4 — used for g and i (damped by the recursion)
__device__ __forceinline__ float tanh_fast(float x) {
    float y;
    asm("tanh.approx.f32 %0, %1;" : "=f"(y) : "f"(x));
    return y;
}
__device__ __forceinline__ float sig_fast(float x) {
    return fmaf(0.5f, tanh_fast(0.5f * x), 0.5f);
}

// ---------------------------------------------------------------------------
// prep_kernel: W (g,i,f) fp32 -> fp16 global, layout [g][b][h][i].
// grid = 768 (plane*4 + quarter), block = 256.
// ---------------------------------------------------------------------------
__global__ void prep_kernel(const float* __restrict__ wg,
                            const float* __restrict__ wi,
                            const float* __restrict__ wf)
{
    const int plane = blockIdx.x >> 2;          // g*64 + b
    const int quarter = blockIdx.x & 3;
    const int g = plane >> 6, b = plane & 63;
    const float* src = ((g == 0) ? wg : (g == 1) ? wi : wf) + (size_t)b * HDIM * IDIM;
    __half* dst = g_wH + (size_t)plane * HDIM * IDIM;
    const int base = quarter * 512;             // 512 of 2048 8-elt units
    #pragma unroll
    for (int it = 0; it < 2; it++) {
        const int u = base + it * 256 + threadIdx.x;
        const float4* p = (const float4*)(src + u * 8);
        *(uint4*)(dst + u * 8) = cvt8h(p[0], p[1]);
    }
}

// 8 k-steps of m32n16 fp16 MMA against the shared x tile
__device__ __forceinline__ void gate_mma(uint32_t a_row, uint32_t acl,
                                         uint32_t b_row, uint32_t bcl,
                                         uint32_t rxor, uint32_t wofs,
                                         float (&d)[2][2][4]) {
    #pragma unroll
    for (int mi = 0; mi < 2; mi++)
        #pragma unroll
        for (int ni = 0; ni < 2; ni++)
            #pragma unroll
            for (int k = 0; k < 4; k++) d[mi][ni][k] = 0.0f;
    #pragma unroll
    for (int kk = 0; kk < 8; kk++) {
        const uint32_t kb = (uint32_t)kk << 5;
        uint32_t a0[4], a1[4], bb[4];
        const uint32_t aaddr = a_row + wofs + ((kb + acl) ^ rxor);
        ldsm_x4(a0, aaddr);
        ldsm_x4(a1, aaddr + 16 * 256);
        ldsm_x4(bb, b_row + ((kb + bcl) ^ rxor));
        mma_f16(d[0][0], a0, bb[0], bb[1]);
        mma_f16(d[0][1], a0, bb[2], bb[3]);
        mma_f16(d[1][0], a1, bb[0], bb[1]);
        mma_f16(d[1][1], a1, bb[2], bb[3]);
    }
}

// ---------------------------------------------------------------------------
// gates_kernel: grid (CHUNKS, BATCH) = (32, 64); block 512 (16 warps), occ 2.
// Warp grid 4m x 4n, warp tile m32 x n16 over the 128h x 64t chunk.
// Activations: g,i via 1-MUFU tanh.approx; f exact (2 MUFU).
// ---------------------------------------------------------------------------
__global__ void __launch_bounds__(NTH, 2)
gates_kernel(const float* __restrict__ x,
             const float* __restrict__ bg, const float* __restrict__ bi,
             const float* __restrict__ bf_)
{
    extern __shared__ char smem[];
    const uint32_t sb = smem_u32(smem);
    const int tid  = threadIdx.x;
    const int wid  = tid >> 5;
    const int lane = tid & 31;
    const int b  = blockIdx.y;
    const int ch = blockIdx.x;
    const int t0 = ch * TCH;

    // ---- cp.async all 3 gate W tiles (fp16, swizzled 256B rows) ----
    #pragma unroll
    for (int it = 0; it < 12; it++) {                 // 6144 16B units
        const int u = tid + it * NTH;
        const int g = u >> 11, rem = u & 2047;
        const int row = rem >> 4, cb = (rem & 15) << 4;       // col bytes
        const __half* src = g_wH + ((size_t)(g * BATCH + b) * (HDIM * IDIM))
                                 + row * IDIM + (cb >> 1);
        cp_async16(sb + SM_W + g * 32768 + row * 256 + (cb ^ ((row & 7) << 4)), src);
    }
    // ---- x chunk: 1024 16B units -> fp16 swizzled (overlaps cp.async) ----
    #pragma unroll
    for (int it = 0; it < 2; it++) {
        const int u = tid + it * NTH;
        const int row = u >> 4, cb = (u & 15) << 4;           // col bytes (fp16)
        const float4* p = (const float4*)(x + (size_t)(t0 + row) * (BATCH * IDIM)
                                            + (size_t)b * IDIM + (cb >> 1));
        *(uint4*)(smem + SM_X + row * 256 + (cb ^ ((row & 7) << 4))) = cvt8h(p[0], p[1]);
    }
    cp_commit_wait();
    __syncthreads();

    // ---- warp tiling: 4m x 4n; warp tile m32 x n16 ----
    const int wm = wid >> 2, wn = wid & 3;
    const int m0 = wm * 32, n0 = wn * 16;
    const int j  = lane & 3;                    // t-pair index within quad
    const int r  = lane >> 2;                   // row-within-8

    const uint32_t rxor  = (uint32_t)((lane & 7) << 4);
    const uint32_t a_row = sb + SM_W + (uint32_t)(m0 + (lane & 15)) * 256;
    const uint32_t acl   = (uint32_t)((lane >> 4) << 4);
    const uint32_t b_row = sb + SM_X
                         + (uint32_t)(n0 + (lane & 7) + ((lane >> 4) << 3)) * 256;
    const uint32_t bcl   = (uint32_t)(((lane >> 3) & 1) << 4);

    float d[2][2][4];

    // ---- gate g (tanh.approx) -> G ----
    float G[2][2][4];
    gate_mma(a_row, acl, b_row, bcl, rxor, 0u, d);
    #pragma unroll
    for (int mi = 0; mi < 2; mi++) {
        const float b0 = bg[b * HDIM + m0 + 16 * mi + r];
        const float b1 = bg[b * HDIM + m0 + 16 * mi + 8 + r];
        #pragma unroll
        for (int ni = 0; ni < 2; ni++)
            #pragma unroll
            for (int k = 0; k < 4; k++)
                G[mi][ni][k] = tanh_fast(d[mi][ni][k] + ((k >> 1) ? b1 : b0));
    }

    // ---- gate i (sigmoid via tanh.approx) -> E = i * g (G freed) ----
    float E[2][2][4];
    gate_mma(a_row, acl, b_row, bcl, rxor, 32768u, d);
    #pragma unroll
    for (int mi = 0; mi < 2; mi++) {
        const float b0 = bi[b * HDIM + m0 + 16 * mi + r];
        const float b1 = bi[b * HDIM + m0 + 16 * mi + 8 + r];
        #pragma unroll
        for (int ni = 0; ni < 2; ni++)
            #pragma unroll
            for (int k = 0; k < 4; k++)
                E[mi][ni][k] = sig_fast(d[mi][ni][k] + ((k >> 1) ? b1 : b0)) * G[mi][ni][k];
    }

    // ---- gate f (EXACT sigmoid), folded straight into the pair-compose ----
    float A[2][2][2], Bv[2][2][2];              // [mi][hi][ni]
    gate_mma(a_row, acl, b_row, bcl, rxor, 65536u, d);
    #pragma unroll
    for (int mi = 0; mi < 2; mi++) {
        const float b0 = bf_[b * HDIM + m0 + 16 * mi + r];
        const float b1 = bf_[b * HDIM + m0 + 16 * mi + 8 + r];
        #pragma unroll
        for (int hi = 0; hi < 2; hi++) {
            const float bb_ = hi ? b1 : b0;
            #pragma unroll
            for (int ni = 0; ni < 2; ni++) {
                const float f0 = fsig(d[mi][ni][2 * hi]     + bb_);
                const float f1 = fsig(d[mi][ni][2 * hi + 1] + bb_);
                const float e0 = E[mi][ni][2 * hi], e1 = E[mi][ni][2 * hi + 1];
                A[mi][hi][ni]  = f1 * f0;
                Bv[mi][hi][ni] = f1 * e0 + e1;
            }
        }
    }

    // ---- quad scan over j (width-4 inclusive affine scan, ascending t) ----
    #pragma unroll
    for (int delta = 1; delta <= 2; delta <<= 1) {
        #pragma unroll
        for (int mi = 0; mi < 2; mi++)
            #pragma unroll
            for (int hi = 0; hi < 2; hi++)
                #pragma unroll
                for (int ni = 0; ni < 2; ni++) {
                    const float pA = __shfl_up_sync(0xffffffffu, A[mi][hi][ni],  delta, 4);
                    const float pB = __shfl_up_sync(0xffffffffu, Bv[mi][hi][ni], delta, 4);
                    if (j >= delta) {
                        Bv[mi][hi][ni] = A[mi][hi][ni] * pB + Bv[mi][hi][ni];
                        A[mi][hi][ni]  = A[mi][hi][ni] * pA;
                    }
                }
    }

    __syncthreads();                            // x tile dead -> reuse as seg
    float2* seg = (float2*)(smem + SM_X);       // [HDIM][4 n-warps]
    if (j == 3) {
        #pragma unroll
        for (int mi = 0; mi < 2; mi++)
            #pragma unroll
            for (int hi = 0; hi < 2; hi++) {
                const float At = A[mi][hi][1] * A[mi][hi][0];
                const float Bt = A[mi][hi][1] * Bv[mi][hi][0] + Bv[mi][hi][1];
                const int h = m0 + 16 * mi + 8 * hi + r;
                seg[h * 4 + wn] = make_float2(At, Bt);
            }
    }
    __syncthreads();

    if (tid < HDIM) {
        const int h = tid;
        const float2 s0 = seg[h * 4 + 0];
        float At = s0.x, Bt = s0.y;
        #pragma unroll
        for (int s = 1; s < 4; s++) {
            const float2 ss = seg[h * 4 + s];
            Bt = ss.x * Bt + ss.y;
            At = ss.x * At;
        }
        g_AB[(b * CHUNKS + ch) * HDIM + h] = make_float2(At, Bt);
    }
}

// ---------------------------------------------------------------------------
// final_kernel: grid = BATCH, block = 512. thread = (seg, h) with seg = tid>>7.
// All 4 segs compose 8 chunk-affines in parallel; seg-1 threads concurrently
// do the o-gate dot (t = T-1); combine via smem; classifier head on seg 0.
// ---------------------------------------------------------------------------
__global__ void __launch_bounds__(512)
final_kernel(const float* __restrict__ x,
             const float* __restrict__ wo, const float* __restrict__ bo,
             const float* __restrict__ fc1w, const float* __restrict__ fc1b,
             const float* __restrict__ fc2w, const float* __restrict__ fc2b,
             float* __restrict__ out)
{
    __shared__ float4 xrow[IDIM / 4];
    __shared__ float2 segs[4 * HDIM];
    __shared__ float  opre_s[HDIM];
    __shared__ float  hs[HDIM];
    __shared__ float  zs[FCDIM];
    __shared__ float  z2[ODIM];

    const int b   = blockIdx.x;
    const int tid = threadIdx.x;
    const int h   = tid & 127;
    const int sg  = tid >> 7;

    if (tid < IDIM / 4)
        xrow[tid] = ((const float4*)(x + (size_t)(T_LEN - 1) * (BATCH * IDIM) + b * IDIM))[tid];

    // every thread: front-batched load of its 8 chunk affines
    float2 AB[CHUNKS / 4];
    #pragma unroll
    for (int k = 0; k < CHUNKS / 4; k++)
        AB[k] = g_AB[(b * CHUNKS + sg * (CHUNKS / 4) + k) * HDIM + h];
    __syncthreads();                    // xrow visible

    // seg-1 threads: o-gate pre-activation dot (concurrent with composes)
    if (sg == 1) {
        float opre = bo[b * HDIM + h];
        const float4* wr = (const float4*)(wo + ((size_t)b * HDIM + h) * IDIM);
        #pragma unroll 8
        for (int k = 0; k < IDIM / 4; k++) {
            const float4 w4 = wr[k], x4 = xrow[k];
            opre += w4.x * x4.x + w4.y * x4.y + w4.z * x4.z + w4.w * x4.w;
        }
        opre_s[h] = opre;
    }

    // all threads: compose own chunks (ascending)
    float At = AB[0].x, Bt = AB[0].y;
    #pragma unroll
    for (int k = 1; k < CHUNKS / 4; k++) {
        Bt = AB[k].x * Bt + AB[k].y;
        At = AB[k].x * At;
    }
    segs[sg * HDIM + h] = make_float2(At, Bt);
    __syncthreads();

    if (sg == 0) {
        float c = Bt;                    // own seg (s=0) already composed
        #pragma unroll
        for (int s = 1; s < 4; s++) {
            const float2 ss = segs[s * HDIM + h];
            c = ss.x * c + ss.y;
        }
        const float o = 1.0f / (1.0f + expf(-opre_s[h]));
        hs[h] = o * tanhf(c);
    }
    __syncthreads();

    if (tid < FCDIM) {
        float z = fc1b[tid];
        const float4* w4p = (const float4*)(fc1w + tid * HDIM);
        #pragma unroll 8
        for (int k = 0; k < HDIM / 4; k++) {
            const float4 w4 = w4p[k];
            z += w4.x * hs[4 * k] + w4.y * hs[4 * k + 1]
               + w4.z * hs[4 * k + 2] + w4.w * hs[4 * k + 3];
        }
        zs[tid] = tanhf(z);
    }
    __syncthreads();

    if (tid < ODIM) {
        float z = fc2b[tid];
        #pragma unroll
        for (int k = 0; k < FCDIM; k++) z += fc2w[tid * FCDIM + k] * zs[k];
        z2[tid] = z;
    }
    __syncthreads();

    if (tid == 0) {
        const float m   = fmaxf(z2[0], z2[1]);
        const float lse = m + logf(expf(z2[0] - m) + expf(z2[1] - m));
        out[b * ODIM + 0] = z2[0] - lse;
        out[b * ODIM + 1] = z2[1] - lse;
    }
}

// ---------------------------------------------------------------------------
extern "C" void kernel_launch(void* const* d_in, const int* in_sizes, int n_in,
                              void* d_out, int out_size)
{
    const float* x   = (const float*)d_in[0];
    const float* wg  = (const float*)d_in[1];
    const float* wi  = (const float*)d_in[2];
    const float* wf  = (const float*)d_in[3];
    const float* wo  = (const float*)d_in[4];
    // d_in[5..8] (recurrent weights) multiply a zero hidden state -> unused.
    const float* bg  = (const float*)d_in[9];
    const float* bi  = (const float*)d_in[10];
    const float* bf  = (const float*)d_in[11];
    const float* bo  = (const float*)d_in[12];
    const float* f1w = (const float*)d_in[13];
    const float* f1b = (const float*)d_in[14];
    const float* f2w = (const float*)d_in[15];
    const float* f2b = (const float*)d_in[16];

    cudaFuncSetAttribute(gates_kernel,
                         cudaFuncAttributeMaxDynamicSharedMemorySize, SM_TOTAL);

    prep_kernel<<<3 * BATCH * 4, 256>>>(wg, wi, wf);
    gates_kernel<<<dim3(CHUNKS, BATCH), NTH, SM_TOTAL>>>(x, bg, bi, bf);
    final_kernel<<<BATCH, 512>>>(x, wo, bo, f1w, f1b, f2w, f2b, (float*)d_out);
}

// round 16
// speedup vs baseline: 1.1271x; 1.1271x over previous
#include <cuda_runtime.h>
#include <cuda_fp16.h>
#include <cstdint>

// ---------------- problem constants ----------------
#define T_LEN   2048
#define BATCH   64
#define IDIM    128
#define HDIM    128
#define FCDIM   32
#define ODIM    2
#define TCH     32                  // timesteps per chunk (MMA N)
#define CHUNKS  (T_LEN / TCH)       // 64
#define NTH     512                 // 16 warps: 8m x 2n, warp tile m16 x n16

// ---------------- global scratch -------------------------------------------
__device__ __align__(16) __half g_wH[3 * BATCH * HDIM * IDIM];  // fp16 W (g,i,f)
__device__ float2 g_AB[BATCH * CHUNKS * HDIM];                  // chunk affine (A,B)

// ---------------- SMEM layout (bytes) --------------------------------------
// x tile 32 x 256B = 8192 | W tiles 3 x 128 x 256B = 98304.
// seg (float2[128][2] = 2KB) aliases the x region after the mainloop.
#define SM_X     0
#define SM_W     8192
#define SM_TOTAL 106496             // x2 CTAs = 212992 <= 228KB/SM

// ---------------- helpers ---------------------------------------------------
__device__ __forceinline__ uint32_t smem_u32(const void* p) {
    uint32_t a;
    asm("{ .reg .u64 t; cvta.to.shared.u64 t, %1; cvt.u32.u64 %0, t; }"
        : "=r"(a) : "l"(p));
    return a;
}
__device__ __forceinline__ void cp_async16(uint32_t dst, const void* src) {
    asm volatile("cp.async.cg.shared.global [%0], [%1], 16;"
                 :: "r"(dst), "l"(src) : "memory");
}
__device__ __forceinline__ void cp_commit_wait() {
    asm volatile("cp.async.commit_group;" ::: "memory");
    asm volatile("cp.async.wait_group 0;" ::: "memory");
}
__device__ __forceinline__ void ldsm_x4(uint32_t (&r)[4], uint32_t addr) {
    asm volatile("ldmatrix.sync.aligned.m8n8.x4.shared.b16 {%0,%1,%2,%3}, [%4];"
                 : "=r"(r[0]), "=r"(r[1]), "=r"(r[2]), "=r"(r[3]) : "r"(addr));
}
__device__ __forceinline__ void mma_f16(float (&d)[4], const uint32_t (&a)[4],
                                        uint32_t b0, uint32_t b1) {
    asm volatile("mma.sync.aligned.m16n8k16.row.col.f32.f16.f16.f32 "
                 "{%0,%1,%2,%3}, {%4,%5,%6,%7}, {%8,%9}, {%0,%1,%2,%3};"
                 : "+f"(d[0]), "+f"(d[1]), "+f"(d[2]), "+f"(d[3])
                 : "r"(a[0]), "r"(a[1]), "r"(a[2]), "r"(a[3]), "r"(b0), "r"(b1));
}
// pack 8 fp32 -> 8 fp16
__device__ __forceinline__ uint4 cvt8h(float4 a, float4 b) {
    uint4 r;
    r.x = __half_as_ushort(__float2half_rn(a.x)) |
          ((uint32_t)__half_as_ushort(__float2half_rn(a.y)) << 16);
    r.y = __half_as_ushort(__float2half_rn(a.z)) |
          ((uint32_t)__half_as_ushort(__float2half_rn(a.w)) << 16);
    r.z = __half_as_ushort(__float2half_rn(b.x)) |
          ((uint32_t)__half_as_ushort(__float2half_rn(b.y)) << 16);
    r.w = __half_as_ushort(__float2half_rn(b.z)) |
          ((uint32_t)__half_as_ushort(__float2half_rn(b.w)) << 16);
    return r;
}
__device__ __forceinline__ float fsig(float x)  { return 1.0f / (1.0f + __expf(-x)); }
__device__ __forceinline__ float ftanh(float x) { return 2.0f * fsig(2.0f * x) - 1.0f; }

// ---------------------------------------------------------------------------
// prep_kernel: W (g,i,f) fp32 -> fp16 global, layout [g][b][h][i].
// grid = 768 (plane*4 + quarter), block = 256.
// ---------------------------------------------------------------------------
__global__ void prep_kernel(const float* __restrict__ wg,
                            const float* __restrict__ wi,
                            const float* __restrict__ wf)
{
    const int plane = blockIdx.x >> 2;          // g*64 + b
    const int quarter = blockIdx.x & 3;
    const int g = plane >> 6, b = plane & 63;
    const float* src = ((g == 0) ? wg : (g == 1) ? wi : wf) + (size_t)b * HDIM * IDIM;
    __half* dst = g_wH + (size_t)plane * HDIM * IDIM;
    const int base = quarter * 512;             // 512 of 2048 8-elt units
    #pragma unroll
    for (int it = 0; it < 2; it++) {
        const int u = base + it * 256 + threadIdx.x;
        const float4* p = (const float4*)(src + u * 8);
        *(uint4*)(dst + u * 8) = cvt8h(p[0], p[1]);
    }
}

// ---------------------------------------------------------------------------
// gates_kernel: grid (CHUNKS, BATCH) = (64, 64); block 512 (16 warps), occ 2.
// Warp grid 8m x 2n, warp tile m16 x n16 over the 128h x 32t chunk.
// k-step-outer / gate-inner mainloop: the B(x) fragment is loaded ONCE per
// k-step and reused by all 3 gate GEMMs (B LDSM traffic /3; A redundancy /2
// vs the 4n configs), with 3 live accumulator sets for MMA/LDSM overlap.
// ---------------------------------------------------------------------------
__global__ void __launch_bounds__(NTH, 2)
gates_kernel(const float* __restrict__ x,
             const float* __restrict__ bg, const float* __restrict__ bi,
             const float* __restrict__ bf_)
{
    extern __shared__ char smem[];
    const uint32_t sb = smem_u32(smem);
    const int tid  = threadIdx.x;
    const int wid  = tid >> 5;
    const int lane = tid & 31;
    const int b  = blockIdx.y;
    const int ch = blockIdx.x;
    const int t0 = ch * TCH;

    // ---- cp.async all 3 gate W tiles (fp16, swizzled 256B rows) ----
    #pragma unroll
    for (int it = 0; it < 12; it++) {                 // 6144 16B units
        const int u = tid + it * NTH;
        const int g = u >> 11, rem = u & 2047;
        const int row = rem >> 4, cb = (rem & 15) << 4;       // col bytes
        const __half* src = g_wH + ((size_t)(g * BATCH + b) * (HDIM * IDIM))
                                 + row * IDIM + (cb >> 1);
        cp_async16(sb + SM_W + g * 32768 + row * 256 + (cb ^ ((row & 7) << 4)), src);
    }
    // ---- x chunk: 512 16B units -> fp16 swizzled (overlaps cp.async) ----
    {
        const int row = tid >> 4, cb = (tid & 15) << 4;       // col bytes (fp16)
        const float4* p = (const float4*)(x + (size_t)(t0 + row) * (BATCH * IDIM)
                                            + (size_t)b * IDIM + (cb >> 1));
        *(uint4*)(smem + SM_X + row * 256 + (cb ^ ((row & 7) << 4))) = cvt8h(p[0], p[1]);
    }
    cp_commit_wait();
    __syncthreads();

    // ---- warp tiling: 8m x 2n; warp tile m16 x n16 ----
    const int wm = wid >> 1, wn = wid & 1;
    const int m0 = wm * 16, n0 = wn * 16;
    const int j  = lane & 3;                    // t-pair index within quad
    const int r  = lane >> 2;                   // row-within-8

    const uint32_t rxor  = (uint32_t)((lane & 7) << 4);
    const uint32_t a_row = sb + SM_W + (uint32_t)(m0 + (lane & 15)) * 256;
    const uint32_t acl   = (uint32_t)((lane >> 4) << 4);
    // B x4 (n16): lanes 0-7 rows n0..n0+7 (k0-7), 8-15 same rows (k8-15),
    //             16-23 rows n0+8..n0+15 (k0-7), 24-31 (k8-15)
    const uint32_t b_row = sb + SM_X
                         + (uint32_t)(n0 + (lane & 7) + ((lane >> 4) << 3)) * 256;
    const uint32_t bcl   = (uint32_t)(((lane >> 3) & 1) << 4);

    // ---- mainloop: kstep outer, gate inner (bb shared across gates) ----
    float d[3][2][4];                           // [gate][ni][frag]
    #pragma unroll
    for (int g = 0; g < 3; g++)
        #pragma unroll
        for (int ni = 0; ni < 2; ni++)
            #pragma unroll
            for (int k = 0; k < 4; k++) d[g][ni][k] = 0.0f;

    #pragma unroll
    for (int kk = 0; kk < 8; kk++) {
        const uint32_t kb = (uint32_t)kk << 5;
        uint32_t bb[4];
        ldsm_x4(bb, b_row + ((kb + bcl) ^ rxor));
        #pragma unroll
        for (int g = 0; g < 3; g++) {
            uint32_t aa[4];
            ldsm_x4(aa, a_row + (uint32_t)g * 32768u + ((kb + acl) ^ rxor));
            mma_f16(d[g][0], aa, bb[0], bb[1]);
            mma_f16(d[g][1], aa, bb[2], bb[3]);
        }
    }

    // ---- activations (numerics identical to the 101us round-13 kernel) ----
    // thread owns h rows: m0 + 8*hi + r (hi = k>>1); t = n0 + ni*8 + 2*j + (k&1)
    float G[2][4];
    {
        const float b0 = bg[b * HDIM + m0 + r];
        const float b1 = bg[b * HDIM + m0 + 8 + r];
        #pragma unroll
        for (int ni = 0; ni < 2; ni++)
            #pragma unroll
            for (int k = 0; k < 4; k++)
                G[ni][k] = ftanh(d[0][ni][k] + ((k >> 1) ? b1 : b0));
    }
    float E[2][4];
    {
        const float b0 = bi[b * HDIM + m0 + r];
        const float b1 = bi[b * HDIM + m0 + 8 + r];
        #pragma unroll
        for (int ni = 0; ni < 2; ni++)
            #pragma unroll
            for (int k = 0; k < 4; k++)
                E[ni][k] = fsig(d[1][ni][k] + ((k >> 1) ? b1 : b0)) * G[ni][k];
    }
    // f gate folded straight into the pair-compose
    float A[2][2], Bv[2][2];                    // [hi][ni]
    {
        const float b0 = bf_[b * HDIM + m0 + r];
        const float b1 = bf_[b * HDIM + m0 + 8 + r];
        #pragma unroll
        for (int hi = 0; hi < 2; hi++) {
            const float bb_ = hi ? b1 : b0;
            #pragma unroll
            for (int ni = 0; ni < 2; ni++) {
                const float f0 = fsig(d[2][ni][2 * hi]     + bb_);
                const float f1 = fsig(d[2][ni][2 * hi + 1] + bb_);
                const float e0 = E[ni][2 * hi], e1 = E[ni][2 * hi + 1];
                A[hi][ni]  = f1 * f0;
                Bv[hi][ni] = f1 * e0 + e1;
            }
        }
    }

    // ---- quad scan over j (width-4 inclusive affine scan, ascending t) ----
    #pragma unroll
    for (int delta = 1; delta <= 2; delta <<= 1) {
        #pragma unroll
        for (int hi = 0; hi < 2; hi++)
            #pragma unroll
            for (int ni = 0; ni < 2; ni++) {
                const float pA = __shfl_up_sync(0xffffffffu, A[hi][ni],  delta, 4);
                const float pB = __shfl_up_sync(0xffffffffu, Bv[hi][ni], delta, 4);
                if (j >= delta) {
                    Bv[hi][ni] = A[hi][ni] * pB + Bv[hi][ni];
                    A[hi][ni]  = A[hi][ni] * pA;
                }
            }
    }

    __syncthreads();                            // x tile dead -> reuse as seg
    float2* seg = (float2*)(smem + SM_X);       // [HDIM][2 n-warps]
    if (j == 3) {
        #pragma unroll
        for (int hi = 0; hi < 2; hi++) {
            // ni compose (ni=0 covers t n0..n0+7, ni=1 t n0+8..n0+15)
            const float At = A[hi][1] * A[hi][0];
            const float Bt = A[hi][1] * Bv[hi][0] + Bv[hi][1];
            const int h = m0 + 8 * hi + r;
            seg[h * 2 + wn] = make_float2(At, Bt);
        }
    }
    __syncthreads();

    if (tid < HDIM) {
        const int h = tid;
        const float2 s0 = seg[h * 2 + 0];
        const float2 s1 = seg[h * 2 + 1];
        g_AB[(b * CHUNKS + ch) * HDIM + h] =
            make_float2(s1.x * s0.x, s1.x * s0.y + s1.y);
    }
}

// ---------------------------------------------------------------------------
// final_kernel: grid = BATCH, block = 512. thread = (seg, h) with seg = tid>>7.
// All 4 segs compose 16 chunk-affines in parallel; seg-1 threads concurrently
// do the o-gate dot (t = T-1); combine via smem; classifier head on seg 0.
// ---------------------------------------------------------------------------
__global__ void __launch_bounds__(512)
final_kernel(const float* __restrict__ x,
             const float* __restrict__ wo, const float* __restrict__ bo,
             const float* __restrict__ fc1w, const float* __restrict__ fc1b,
             const float* __restrict__ fc2w, const float* __restrict__ fc2b,
             float* __restrict__ out)
{
    __shared__ float4 xrow[IDIM / 4];
    __shared__ float2 segs[4 * HDIM];
    __shared__ float  opre_s[HDIM];
    __shared__ float  hs[HDIM];
    __shared__ float  zs[FCDIM];
    __shared__ float  z2[ODIM];

    const int b   = blockIdx.x;
    const int tid = threadIdx.x;
    const int h   = tid & 127;
    const int sg  = tid >> 7;

    if (tid < IDIM / 4)
        xrow[tid] = ((const float4*)(x + (size_t)(T_LEN - 1) * (BATCH * IDIM) + b * IDIM))[tid];

    // every thread: front-batched load of its 16 chunk affines
    float2 AB[CHUNKS / 4];
    #pragma unroll
    for (int k = 0; k < CHUNKS / 4; k++)
        AB[k] = g_AB[(b * CHUNKS + sg * (CHUNKS / 4) + k) * HDIM + h];
    __syncthreads();                    // xrow visible

    // seg-1 threads: o-gate pre-activation dot (concurrent with composes)
    if (sg == 1) {
        float opre = bo[b * HDIM + h];
        const float4* wr = (const float4*)(wo + ((size_t)b * HDIM + h) * IDIM);
        #pragma unroll 8
        for (int k = 0; k < IDIM / 4; k++) {
            const float4 w4 = wr[k], x4 = xrow[k];
            opre += w4.x * x4.x + w4.y * x4.y + w4.z * x4.z + w4.w * x4.w;
        }
        opre_s[h] = opre;
    }

    // all threads: compose own chunks (ascending)
    float At = AB[0].x, Bt = AB[0].y;
    #pragma unroll
    for (int k = 1; k < CHUNKS / 4; k++) {
        Bt = AB[k].x * Bt + AB[k].y;
        At = AB[k].x * At;
    }
    segs[sg * HDIM + h] = make_float2(At, Bt);
    __syncthreads();

    if (sg == 0) {
        float c = Bt;                    // own seg (s=0) already composed
        #pragma unroll
        for (int s = 1; s < 4; s++) {
            const float2 ss = segs[s * HDIM + h];
            c = ss.x * c + ss.y;
        }
        const float o = 1.0f / (1.0f + expf(-opre_s[h]));
        hs[h] = o * tanhf(c);
    }
    __syncthreads();

    if (tid < FCDIM) {
        float z = fc1b[tid];
        const float4* w4p = (const float4*)(fc1w + tid * HDIM);
        #pragma unroll 8
        for (int k = 0; k < HDIM / 4; k++) {
            const float4 w4 = w4p[k];
            z += w4.x * hs[4 * k] + w4.y * hs[4 * k + 1]
               + w4.z * hs[4 * k + 2] + w4.w * hs[4 * k + 3];
        }
        zs[tid] = tanhf(z);
    }
    __syncthreads();

    if (tid < ODIM) {
        float z = fc2b[tid];
        #pragma unroll
        for (int k = 0; k < FCDIM; k++) z += fc2w[tid * FCDIM + k] * zs[k];
        z2[tid] = z;
    }
    __syncthreads();

    if (tid == 0) {
        const float m   = fmaxf(z2[0], z2[1]);
        const float lse = m + logf(expf(z2[0] - m) + expf(z2[1] - m));
        out[b * ODIM + 0] = z2[0] - lse;
        out[b * ODIM + 1] = z2[1] - lse;
    }
}

// ---------------------------------------------------------------------------
extern "C" void kernel_launch(void* const* d_in, const int* in_sizes, int n_in,
                              void* d_out, int out_size)
{
    const float* x   = (const float*)d_in[0];
    const float* wg  = (const float*)d_in[1];
    const float* wi  = (const float*)d_in[2];
    const float* wf  = (const float*)d_in[3];
    const float* wo  = (const float*)d_in[4];
    // d_in[5..8] (recurrent weights) multiply a zero hidden state -> unused.
    const float* bg  = (const float*)d_in[9];
    const float* bi  = (const float*)d_in[10];
    const float* bf  = (const float*)d_in[11];
    const float* bo  = (const float*)d_in[12];
    const float* f1w = (const float*)d_in[13];
    const float* f1b = (const float*)d_in[14];
    const float* f2w = (const float*)d_in[15];
    const float* f2b = (const float*)d_in[16];

    cudaFuncSetAttribute(gates_kernel,
                         cudaFuncAttributeMaxDynamicSharedMemorySize, SM_TOTAL);

    prep_kernel<<<3 * BATCH * 4, 256>>>(wg, wi, wf);
    gates_kernel<<<dim3(CHUNKS, BATCH), NTH, SM_TOTAL>>>(x, bg, bi, bf);
    final_kernel<<<BATCH, 512>>>(x, wo, bo, f1w, f1b, f2w, f2b, (float*)d_out);
}